// round 2
// baseline (speedup 1.0000x reference)
#include <cuda_runtime.h>
#include <cuda_bf16.h>

#define N_NODES 50000
#define NEDGE   800000
#define ETOT    850000      // edges + self loops
#define C       128
#define H       8
#define NEG_SLOPE 0.2f

// ---------------- scratch (static device globals; no allocation) ----------------
__device__ __align__(16) float g_h[N_NODES * C];        // projected features
__device__ __align__(16) float g_acc[N_NODES * C];      // aggregated messages
__device__ float g_asrc[N_NODES * H];
__device__ float g_adst[N_NODES * H];
__device__ float g_ex[ETOT * H];                        // exp(logit) per (edge, head)
__device__ float g_denom[N_NODES * H];
__device__ float g_colsum[C];
__device__ float g_colsq[C];
__device__ float g_scale[C];
__device__ float g_shift[C];

// ---------------- K0: zero accumulators ----------------
__global__ void k_zero_all() {
    int i = blockIdx.x * 256 + threadIdx.x;
    if (i < N_NODES * C) g_acc[i] = 0.f;
    if (i < N_NODES * H) g_denom[i] = 0.f;
    if (i < C) { g_colsum[i] = 0.f; g_colsq[i] = 0.f; }
}

// ---------------- K1: h = x @ W  +  per-node attention halves ----------------
// Block: 256 threads. 32 nodes/block. Thread (cg, ng): cols [4cg,4cg+3], nodes ng*4..ng*4+3.
__global__ void k_gemm(const float* __restrict__ x, const float* __restrict__ W,
                       const float* __restrict__ att_src, const float* __restrict__ att_dst) {
    __shared__ float xs[32][C];
    int base = blockIdx.x * 32;
    int tid  = threadIdx.x;

    // cooperative load of 32 node rows (1024 float4)
    for (int i = tid; i < 32 * 32; i += 256) {
        int node = i >> 5;
        int c4   = i & 31;
        int gn   = base + node;
        float4 v = (gn < N_NODES) ? ((const float4*)x)[gn * 32 + c4]
                                  : make_float4(0.f, 0.f, 0.f, 0.f);
        *(float4*)&xs[node][c4 * 4] = v;
    }
    __syncthreads();

    int cg = tid & 31;    // column group (lane)
    int ng = tid >> 5;    // node group (warp id)

    float4 a0 = make_float4(0.f,0.f,0.f,0.f);
    float4 a1 = a0, a2 = a0, a3 = a0;
    const float4* W4 = (const float4*)W;
    const float* xr0 = xs[ng * 4 + 0];
    const float* xr1 = xs[ng * 4 + 1];
    const float* xr2 = xs[ng * 4 + 2];
    const float* xr3 = xs[ng * 4 + 3];

    #pragma unroll 8
    for (int k = 0; k < C; k++) {
        float4 w = W4[k * 32 + cg];
        float x0 = xr0[k], x1 = xr1[k], x2 = xr2[k], x3 = xr3[k];
        a0.x += w.x * x0; a0.y += w.y * x0; a0.z += w.z * x0; a0.w += w.w * x0;
        a1.x += w.x * x1; a1.y += w.y * x1; a1.z += w.z * x1; a1.w += w.w * x1;
        a2.x += w.x * x2; a2.y += w.y * x2; a2.z += w.z * x2; a2.w += w.w * x2;
        a3.x += w.x * x3; a3.y += w.y * x3; a3.z += w.z * x3; a3.w += w.w * x3;
    }

    float4 as = ((const float4*)att_src)[cg];  // att laid out [H=8, D=16] = 128 floats
    float4 ad = ((const float4*)att_dst)[cg];
    float4 accs[4] = {a0, a1, a2, a3};

    #pragma unroll
    for (int j = 0; j < 4; j++) {
        float4 a = accs[j];
        float ps = a.x*as.x + a.y*as.y + a.z*as.z + a.w*as.w;
        float pd = a.x*ad.x + a.y*ad.y + a.z*ad.z + a.w*ad.w;
        // reduce across the 4 lanes of one head (lanes 4h..4h+3)
        ps += __shfl_xor_sync(0xffffffffu, ps, 1);
        ps += __shfl_xor_sync(0xffffffffu, ps, 2);
        pd += __shfl_xor_sync(0xffffffffu, pd, 1);
        pd += __shfl_xor_sync(0xffffffffu, pd, 2);
        int n = base + ng * 4 + j;
        if (n < N_NODES) {
            ((float4*)g_h)[n * 32 + cg] = a;
            if ((cg & 3) == 0) {
                int hd = cg >> 2;
                g_asrc[n * H + hd] = ps;
                g_adst[n * H + hd] = pd;
            }
        }
    }
}

// ---------------- K2: per-(edge,head) logits -> exp, denom accumulation ----------------
__global__ void k_edge_exp(const int* __restrict__ ei) {
    int tid = blockIdx.x * 256 + threadIdx.x;
    if (tid >= ETOT * H) return;
    int eid = tid >> 3;
    int hd  = tid & 7;
    int s, d;
    if (eid < NEDGE) { s = ei[eid]; d = ei[NEDGE + eid]; }
    else             { s = d = eid - NEDGE; }
    float e = g_asrc[s * H + hd] + g_adst[d * H + hd];
    e = (e > 0.f) ? e : NEG_SLOPE * e;
    // logits are tiny (|e| < ~5): exp without max-subtraction is safe, matches ref to ~1e-7
    float ex = __expf(e);
    g_ex[tid] = ex;
    atomicAdd(&g_denom[d * H + hd], ex);
}

// ---------------- K3: weighted scatter-aggregate ----------------
__global__ void k_scatter(const int* __restrict__ ei) {
    int tid = blockIdx.x * 256 + threadIdx.x;
    if (tid >= ETOT * H) return;
    int eid = tid >> 3;
    int hd  = tid & 7;
    int s, d;
    if (eid < NEDGE) { s = ei[eid]; d = ei[NEDGE + eid]; }
    else             { s = d = eid - NEDGE; }
    float ex    = g_ex[tid];
    float alpha = ex / (g_denom[d * H + hd] + 1e-16f);

    const float4* hv = (const float4*)(g_h + (size_t)s * C + hd * 16);
    float* ap = g_acc + (size_t)d * C + hd * 16;
    #pragma unroll
    for (int i = 0; i < 4; i++) {
        float4 v = hv[i];
        v.x *= alpha; v.y *= alpha; v.z *= alpha; v.w *= alpha;
        asm volatile("red.global.add.v4.f32 [%0], {%1,%2,%3,%4};"
                     :: "l"(ap + i * 4), "f"(v.x), "f"(v.y), "f"(v.z), "f"(v.w)
                     : "memory");
    }
}

// ---------------- K4: BN column statistics ----------------
__global__ void k_stats(const float* __restrict__ bias) {
    int c    = threadIdx.x & (C - 1);
    int half = threadIdx.x >> 7;       // 0 or 1
    float b = bias[c];
    float s = 0.f, ss = 0.f;
    for (int r = blockIdx.x * 2 + half; r < N_NODES; r += gridDim.x * 2) {
        float v = g_acc[r * C + c] + b;
        s  += v;
        ss += v * v;
    }
    atomicAdd(&g_colsum[c], s);
    atomicAdd(&g_colsq[c], ss);
}

// ---------------- K4b: fold stats into scale/shift ----------------
__global__ void k_scale(const float* __restrict__ gamma, const float* __restrict__ beta) {
    int c = threadIdx.x;
    float inv_n = 1.f / (float)N_NODES;
    float mean = g_colsum[c] * inv_n;
    float var  = g_colsq[c] * inv_n - mean * mean;
    float sc   = gamma[c] * rsqrtf(var + 1e-5f);
    g_scale[c] = sc;
    g_shift[c] = beta[c] - mean * sc;
}

// ---------------- K5: normalize + ReLU ----------------
__global__ void k_final(const float* __restrict__ bias, float* __restrict__ out) {
    int idx = blockIdx.x * 256 + threadIdx.x;
    if (idx >= N_NODES * C) return;
    int c = idx & (C - 1);
    float y = (g_acc[idx] + bias[c]) * g_scale[c] + g_shift[c];
    out[idx] = fmaxf(y, 0.f);
}

// ---------------- launch ----------------
extern "C" void kernel_launch(void* const* d_in, const int* in_sizes, int n_in,
                              void* d_out, int out_size) {
    const float* x       = (const float*)d_in[0];
    const int*   ei      = (const int*)d_in[1];
    const float* W       = (const float*)d_in[2];
    const float* att_src = (const float*)d_in[3];
    const float* att_dst = (const float*)d_in[4];
    const float* bias    = (const float*)d_in[5];
    const float* gamma   = (const float*)d_in[6];
    const float* beta    = (const float*)d_in[7];
    float*       out     = (float*)d_out;

    k_zero_all<<<(N_NODES * C + 255) / 256, 256>>>();
    k_gemm<<<(N_NODES + 31) / 32, 256>>>(x, W, att_src, att_dst);
    int ethreads = ETOT * H;
    k_edge_exp<<<(ethreads + 255) / 256, 256>>>(ei);
    k_scatter<<<(ethreads + 255) / 256, 256>>>(ei);
    k_stats<<<200, 256>>>(bias);
    k_scale<<<1, C>>>(gamma, beta);
    k_final<<<(N_NODES * C + 255) / 256, 256>>>(bias, out);
}

// round 3
// speedup vs baseline: 1.5893x; 1.5893x over previous
#include <cuda_runtime.h>
#include <cuda_bf16.h>

#define N_NODES 50000
#define NEDGE   800000
#define ETOT    850000      // edges + self loops
#define C       128
#define H       8
#define NEG_SLOPE 0.2f
#define SCAN_NBLK 196       // 196*256 = 50176 >= N_NODES

// ---------------- scratch (static device globals; no allocation) ----------------
__device__ __align__(16) float g_h[N_NODES * C];        // projected features
__device__ __align__(16) float g_acc[N_NODES * C];      // aggregated messages
__device__ float g_asrc[N_NODES * H];
__device__ float g_adst[N_NODES * H];
__device__ int   g_deg[N_NODES];
__device__ int   g_excl[N_NODES];    // within-block exclusive scan
__device__ int   g_bsum[SCAN_NBLK];
__device__ int   g_off[N_NODES];
__device__ int   g_cursor[N_NODES];
__device__ int   g_csrc[ETOT];       // edge sources, sorted by destination
__device__ float g_colsum[C];
__device__ float g_colsq[C];
__device__ float g_scale[C];
__device__ float g_shift[C];

// ---------------- K0: zero counters ----------------
__global__ void k_zero() {
    int i = blockIdx.x * 256 + threadIdx.x;
    if (i < N_NODES) g_deg[i] = 0;
    if (i < C) { g_colsum[i] = 0.f; g_colsq[i] = 0.f; }
}

// ---------------- K1: h = x @ W  +  per-node attention halves ----------------
__global__ void k_gemm(const float* __restrict__ x, const float* __restrict__ W,
                       const float* __restrict__ att_src, const float* __restrict__ att_dst) {
    __shared__ float xs[32][C];
    int base = blockIdx.x * 32;
    int tid  = threadIdx.x;

    for (int i = tid; i < 32 * 32; i += 256) {
        int node = i >> 5;
        int c4   = i & 31;
        int gn   = base + node;
        float4 v = (gn < N_NODES) ? ((const float4*)x)[gn * 32 + c4]
                                  : make_float4(0.f, 0.f, 0.f, 0.f);
        *(float4*)&xs[node][c4 * 4] = v;
    }
    __syncthreads();

    int cg = tid & 31;
    int ng = tid >> 5;

    float4 a0 = make_float4(0.f,0.f,0.f,0.f);
    float4 a1 = a0, a2 = a0, a3 = a0;
    const float4* W4 = (const float4*)W;
    const float* xr0 = xs[ng * 4 + 0];
    const float* xr1 = xs[ng * 4 + 1];
    const float* xr2 = xs[ng * 4 + 2];
    const float* xr3 = xs[ng * 4 + 3];

    #pragma unroll 8
    for (int k = 0; k < C; k++) {
        float4 w = W4[k * 32 + cg];
        float x0 = xr0[k], x1 = xr1[k], x2 = xr2[k], x3 = xr3[k];
        a0.x += w.x * x0; a0.y += w.y * x0; a0.z += w.z * x0; a0.w += w.w * x0;
        a1.x += w.x * x1; a1.y += w.y * x1; a1.z += w.z * x1; a1.w += w.w * x1;
        a2.x += w.x * x2; a2.y += w.y * x2; a2.z += w.z * x2; a2.w += w.w * x2;
        a3.x += w.x * x3; a3.y += w.y * x3; a3.z += w.z * x3; a3.w += w.w * x3;
    }

    float4 as = ((const float4*)att_src)[cg];
    float4 ad = ((const float4*)att_dst)[cg];
    float4 accs[4] = {a0, a1, a2, a3};

    #pragma unroll
    for (int j = 0; j < 4; j++) {
        float4 a = accs[j];
        float ps = a.x*as.x + a.y*as.y + a.z*as.z + a.w*as.w;
        float pd = a.x*ad.x + a.y*ad.y + a.z*ad.z + a.w*ad.w;
        ps += __shfl_xor_sync(0xffffffffu, ps, 1);
        ps += __shfl_xor_sync(0xffffffffu, ps, 2);
        pd += __shfl_xor_sync(0xffffffffu, pd, 1);
        pd += __shfl_xor_sync(0xffffffffu, pd, 2);
        int n = base + ng * 4 + j;
        if (n < N_NODES) {
            ((float4*)g_h)[n * 32 + cg] = a;
            if ((cg & 3) == 0) {
                int hd = cg >> 2;
                g_asrc[n * H + hd] = ps;
                g_adst[n * H + hd] = pd;
            }
        }
    }
}

// ---------------- CSR build ----------------
__global__ void k_hist(const int* __restrict__ ei) {
    int eid = blockIdx.x * 256 + threadIdx.x;
    if (eid >= ETOT) return;
    int d = (eid < NEDGE) ? ei[NEDGE + eid] : (eid - NEDGE);
    atomicAdd(&g_deg[d], 1);
}

__global__ void k_scan1() {
    __shared__ int s[256];
    int t = threadIdx.x;
    int i = blockIdx.x * 256 + t;
    int v = (i < N_NODES) ? g_deg[i] : 0;
    s[t] = v; __syncthreads();
    #pragma unroll
    for (int o = 1; o < 256; o <<= 1) {
        int a = (t >= o) ? s[t - o] : 0;
        __syncthreads();
        s[t] += a;
        __syncthreads();
    }
    if (i < N_NODES) g_excl[i] = s[t] - v;
    if (t == 255) g_bsum[blockIdx.x] = s[255];
}

__global__ void k_scan2() {
    __shared__ int s[256];
    int t = threadIdx.x;
    int v = (t < SCAN_NBLK) ? g_bsum[t] : 0;
    s[t] = v; __syncthreads();
    #pragma unroll
    for (int o = 1; o < 256; o <<= 1) {
        int a = (t >= o) ? s[t - o] : 0;
        __syncthreads();
        s[t] += a;
        __syncthreads();
    }
    if (t < SCAN_NBLK) g_bsum[t] = s[t] - v;
}

__global__ void k_scan3() {
    int i = blockIdx.x * 256 + threadIdx.x;
    if (i >= N_NODES) return;
    int o = g_excl[i] + g_bsum[blockIdx.x];
    g_off[i]    = o;
    g_cursor[i] = o;
}

__global__ void k_fill(const int* __restrict__ ei) {
    int eid = blockIdx.x * 256 + threadIdx.x;
    if (eid >= ETOT) return;
    int s, d;
    if (eid < NEDGE) { s = ei[eid]; d = ei[NEDGE + eid]; }
    else             { s = d = eid - NEDGE; }
    int pos = atomicAdd(&g_cursor[d], 1);
    g_csrc[pos] = s;
}

// ---------------- K3: warp-per-destination softmax + aggregate ----------------
__global__ void k_aggregate() {
    int warp = blockIdx.x * 8 + (threadIdx.x >> 5);
    if (warp >= N_NODES) return;
    int lane = threadIdx.x & 31;
    int hd   = lane >> 2;            // head for this lane (4 lanes per head)

    int beg = g_off[warp];
    int end = beg + g_deg[warp];
    float adst = g_adst[warp * H + hd];

    // pass 1: denominator per head (each lane computes full sum for its head)
    float den = 0.f;
    for (int p = beg; p < end; p++) {
        int s = g_csrc[p];
        float e = g_asrc[s * H + hd] + adst;
        e = (e > 0.f) ? e : NEG_SLOPE * e;
        den += __expf(e);
    }
    float inv = 1.f / (den + 1e-16f);

    // pass 2: weighted aggregation, registers only
    float4 acc = make_float4(0.f, 0.f, 0.f, 0.f);
    for (int p = beg; p < end; p++) {
        int s = g_csrc[p];
        float e = g_asrc[s * H + hd] + adst;
        e = (e > 0.f) ? e : NEG_SLOPE * e;
        float alpha = __expf(e) * inv;
        float4 v = ((const float4*)g_h)[s * 32 + lane];
        acc.x += alpha * v.x; acc.y += alpha * v.y;
        acc.z += alpha * v.z; acc.w += alpha * v.w;
    }
    ((float4*)g_acc)[warp * 32 + lane] = acc;
}

// ---------------- K4: BN column statistics ----------------
__global__ void k_stats(const float* __restrict__ bias) {
    int c    = threadIdx.x & (C - 1);
    int half = threadIdx.x >> 7;
    float b = bias[c];
    float s = 0.f, ss = 0.f;
    for (int r = blockIdx.x * 2 + half; r < N_NODES; r += gridDim.x * 2) {
        float v = g_acc[r * C + c] + b;
        s  += v;
        ss += v * v;
    }
    atomicAdd(&g_colsum[c], s);
    atomicAdd(&g_colsq[c], ss);
}

__global__ void k_scale(const float* __restrict__ gamma, const float* __restrict__ beta) {
    int c = threadIdx.x;
    float inv_n = 1.f / (float)N_NODES;
    float mean = g_colsum[c] * inv_n;
    float var  = g_colsq[c] * inv_n - mean * mean;
    float sc   = gamma[c] * rsqrtf(var + 1e-5f);
    g_scale[c] = sc;
    g_shift[c] = beta[c] - mean * sc;
}

__global__ void k_final(const float* __restrict__ bias, float* __restrict__ out) {
    int idx = blockIdx.x * 256 + threadIdx.x;
    if (idx >= N_NODES * C) return;
    int c = idx & (C - 1);
    float y = (g_acc[idx] + bias[c]) * g_scale[c] + g_shift[c];
    out[idx] = fmaxf(y, 0.f);
}

// ---------------- launch ----------------
extern "C" void kernel_launch(void* const* d_in, const int* in_sizes, int n_in,
                              void* d_out, int out_size) {
    const float* x       = (const float*)d_in[0];
    const int*   ei      = (const int*)d_in[1];
    const float* W       = (const float*)d_in[2];
    const float* att_src = (const float*)d_in[3];
    const float* att_dst = (const float*)d_in[4];
    const float* bias    = (const float*)d_in[5];
    const float* gamma   = (const float*)d_in[6];
    const float* beta    = (const float*)d_in[7];
    float*       out     = (float*)d_out;

    k_zero<<<(N_NODES + 255) / 256, 256>>>();
    k_gemm<<<(N_NODES + 31) / 32, 256>>>(x, W, att_src, att_dst);
    k_hist<<<(ETOT + 255) / 256, 256>>>(ei);
    k_scan1<<<SCAN_NBLK, 256>>>();
    k_scan2<<<1, 256>>>();
    k_scan3<<<SCAN_NBLK, 256>>>();
    k_fill<<<(ETOT + 255) / 256, 256>>>(ei);
    k_aggregate<<<(N_NODES + 7) / 8, 256>>>();
    k_stats<<<200, 256>>>(bias);
    k_scale<<<1, C>>>(gamma, beta);
    k_final<<<(N_NODES * C + 255) / 256, 256>>>(bias, out);
}